// round 7
// baseline (speedup 1.0000x reference)
#include <cuda_runtime.h>
#include <math.h>

#define B_ 128
#define N_ 512
#define U_ 128
#define MSTEPS 70

// ---------------- device scratch (no runtime allocations allowed) ----------------
__device__ float g_kv [B_*128*N_];     // [b][h*16+d][n]
__device__ float g_vv [B_*128*N_];     // [b][h*16+d][n]
__device__ float g_kvf[B_*U_*N_];      // [b][u][n]
__device__ float g_rec[B_*128];        // [b][h*16+d]
__device__ int   g_route[(MSTEPS+1)*B_];
__device__ float g_flp[B_];
__device__ float g_len[B_];
__device__ float g_loss;
__device__ int   g_done;
__device__ unsigned g_matched[B_];
__device__ int   g_check[B_];
__device__ int   g_target[B_];
__device__ float g_logprob[B_];
__device__ unsigned g_keys[MSTEPS*2];

// ---------------- Threefry-2x32-20 (matches JAX exactly) ----------------
__device__ __forceinline__ void tf2x32(unsigned k0, unsigned k1, unsigned &x0, unsigned &x1) {
    unsigned ks2 = k0 ^ k1 ^ 0x1BD11BDAu;
    x0 += k0; x1 += k1;
#define TFR(r) { x0 += x1; x1 = (x1<<(r)) | (x1>>(32-(r))); x1 ^= x0; }
    TFR(13) TFR(15) TFR(26) TFR(6)
    x0 += k1;  x1 += ks2 + 1u;
    TFR(17) TFR(29) TFR(16) TFR(24)
    x0 += ks2; x1 += k0 + 2u;
    TFR(13) TFR(15) TFR(26) TFR(6)
    x0 += k0;  x1 += k1 + 3u;
    TFR(17) TFR(29) TFR(16) TFR(24)
    x0 += k1;  x1 += ks2 + 4u;
    TFR(13) TFR(15) TFR(26) TFR(6)
    x0 += ks2; x1 += k0 + 5u;
#undef TFR
}

// high-accuracy transcendentals (independent of --use_fast_math)
__device__ __forceinline__ float expf_hi(float x) { return (float)exp((double)x); }
__device__ __forceinline__ float logf_hi(float x) { return (float)log((double)x); }

// ---------------- XLA's fast-tanh rational approximation (f32) ----------------
__device__ __forceinline__ float xla_tanhf(float x) {
    float ax = fabsf(x);
    const float cl = 7.90531110763549805f;
    float xc = fminf(fmaxf(x, -cl), cl);
    float x2 = xc * xc;
    float p = fmaf(x2, -2.76076847742355e-16f, 2.00018790482477e-13f);
    p = fmaf(x2, p, -8.60467152213735e-11f);
    p = fmaf(x2, p,  5.12229709037114e-08f);
    p = fmaf(x2, p,  1.48572235717979e-05f);
    p = fmaf(x2, p,  6.37261928875436e-04f);
    p = fmaf(x2, p,  4.89352455891786e-03f);
    p = p * xc;
    float q = fmaf(x2, 1.19825839466702e-06f, 1.18534705686654e-04f);
    q = fmaf(x2, q, 2.26843463243900e-03f);
    q = fmaf(x2, q, 4.89352518554385e-03f);
    float r = __fdiv_rn(p, q);
    return (ax < 0.0004f) ? x : r;
}

// ---------------- init ----------------
__global__ void k_init(const int* __restrict__ obj, const int* __restrict__ hml) {
    int b = threadIdx.x;  // 128 threads
    for (int i = b; i < (MSTEPS+1)*B_; i += B_) g_route[i] = 0;
    g_flp[b] = 0.f; g_len[b] = 0.f;
    if (b == 0) { g_loss = 0.f; g_done = 0; }
    // jax.random.split(key(42), 70) -- PARTITIONABLE (foldlike) mode:
    // subkey_j = both output words of threefry2x32(key, x0=hi32(j)=0, x1=j)
    if (b < MSTEPS) {
        unsigned x0 = 0u, x1 = (unsigned)b;
        tf2x32(0u, 42u, x0, x1);
        g_keys[2*b]   = x0;
        g_keys[2*b+1] = x1;
    }
    int lz = 0;
    for (int m = 0; m < 16; m++) lz |= (hml[b*16 + m] == 0);
    int hz = __syncthreads_or(lz);
    unsigned mk = 0;
    for (int m = 0; m < 16; m++) {
        int v = hml[b*16 + m]; int mt = 0;
        for (int k = 0; k < 4; k++) mt |= (obj[k] == v);
        if (mt) mk |= (1u << m);
    }
    if (hz) mk |= 1u;
    g_matched[b] = mk;
    g_check[b] = (mk == 0xFFFFu) ? 1 : 0;
}

// ---------------- precompute kv, vv ----------------
__global__ void k_prep_kv(const float* __restrict__ hvec, const float* __restrict__ kv_p,
                          const float* __restrict__ vv_p) {
    int b = blockIdx.y, n0 = blockIdx.x * 8;
    int t = threadIdx.x;  // h*16+d
    __shared__ float hs[8*128];
    for (int i = t; i < 8*128; i += 128)
        hs[i] = hvec[(b*N_ + n0 + (i >> 7))*U_ + (i & 127)];
    __syncthreads();
    float ak[8], av[8];
#pragma unroll
    for (int j = 0; j < 8; j++) { ak[j] = 0.f; av[j] = 0.f; }
    for (int x = 0; x < 128; x++) {
        float kp = kv_p[x*128 + t];
        float vp = vv_p[x*128 + t];
#pragma unroll
        for (int j = 0; j < 8; j++) {
            float hx = hs[j*128 + x];
            ak[j] = fmaf(kp, hx, ak[j]);
            av[j] = fmaf(vp, hx, av[j]);
        }
    }
#pragma unroll
    for (int j = 0; j < 8; j++) {
        g_kv[(b*128 + t)*N_ + n0 + j] = ak[j];
        g_vv[(b*128 + t)*N_ + n0 + j] = av[j];
    }
}

// ---------------- precompute kvf ----------------
__global__ void k_prep_kvf(const float* __restrict__ hvec, const float* __restrict__ W,
                           const float* __restrict__ bias) {
    int b = blockIdx.y, n0 = blockIdx.x * 8;
    int u = threadIdx.x;
    __shared__ float hs[8*128];
    for (int i = u; i < 8*128; i += 128)
        hs[i] = hvec[(b*N_ + n0 + (i >> 7))*U_ + (i & 127)];
    __syncthreads();
    float a[8];
#pragma unroll
    for (int j = 0; j < 8; j++) a[j] = 0.f;
    for (int v = 0; v < 128; v++) {
        float w = W[u*128 + v];
#pragma unroll
        for (int j = 0; j < 8; j++) a[j] = fmaf(w, hs[j*128 + v], a[j]);
    }
    float bb = bias[u];
#pragma unroll
    for (int j = 0; j < 8; j++) g_kvf[(b*128 + u)*N_ + n0 + j] = a[j] + bb;
}

// ---------------- per-step attention ----------------
__global__ void k_att(int t, const float* __restrict__ hvec, const float* __restrict__ hbar,
                      const float* __restrict__ qv_p, const int* __restrict__ adj,
                      const float* __restrict__ vec_1, const float* __restrict__ vec_f) {
    int h = blockIdx.x, b = blockIdx.y;
    int tid = threadIdx.x, lane = tid & 31, wid = tid >> 5;  // 512 threads = 16 warps
    __shared__ float qv_sh[16];
    __shared__ float s_red[16];
    __shared__ float s_part[16][17];
    __shared__ float s_b0, s_b1;

    const float *pv, *fv;
    if (t == 0) { pv = vec_1 + b*U_; fv = vec_f + b*U_; }
    else {
        int previ  = g_route[(t-1)*B_ + b];
        int firsti = g_route[B_ + b];
        pv = hvec + (b*N_ + previ)*U_;
        fv = hvec + (b*N_ + firsti)*U_;
    }
    // qv[b,h,d]: warp wid computes d=wid, reduce over x in [0,384)
    {
        int d = wid;
        float acc = 0.f;
        for (int x = lane; x < 384; x += 32) {
            float c = (x < 128) ? hbar[x] : ((x < 256) ? pv[x-128] : fv[x-256]);
            acc = fmaf(qv_p[x*128 + h*16 + d], c, acc);
        }
        for (int o = 16; o > 0; o >>= 1) acc += __shfl_down_sync(0xffffffffu, acc, o);
        if (lane == 0) qv_sh[d] = acc;
    }
    __syncthreads();

    int n = tid;
    int last  = g_route[t*B_ + b];
    int check = g_check[b];
    float acc = 0.f;
    int base = (b*128 + h*16)*N_ + n;
#pragma unroll
    for (int d = 0; d < 16; d++) acc = fmaf(qv_sh[d], g_kv[base + d*N_], acc);
    float compat = acc * 0.25f;                              // / sqrt(D), exact
    bool adj_ok = adj[last*N_ + n] != 0;
    bool dem_ok = (n == 0) ? (check != 0) : (check == 0);
    float m = adj_ok ? (dem_ok ? compat : -1e10f) : -1e30f;

    // block max
    float v = m;
    for (int o = 16; o > 0; o >>= 1) v = fmaxf(v, __shfl_down_sync(0xffffffffu, v, o));
    if (lane == 0) s_red[wid] = v;
    __syncthreads();
    if (tid == 0) { float x = s_red[0]; for (int i = 1; i < 16; i++) x = fmaxf(x, s_red[i]); s_b0 = x; }
    __syncthreads();
    float mx = s_b0;
    float e = expf_hi(m - mx);
    float sv = e;
    for (int o = 16; o > 0; o >>= 1) sv += __shfl_down_sync(0xffffffffu, sv, o);
    if (lane == 0) s_red[wid] = sv;
    __syncthreads();
    if (tid == 0) { float x = 0.f; for (int i = 0; i < 16; i++) x += s_red[i]; s_b1 = x; }
    __syncthreads();
    float w = __fdiv_rn(e, s_b1);

    // rec[b,h,d] = sum_n w * vv
#pragma unroll
    for (int d = 0; d < 16; d++) {
        float val = w * g_vv[base + d*N_];
        for (int o = 16; o > 0; o >>= 1) val += __shfl_down_sync(0xffffffffu, val, o);
        if (lane == 0) s_part[wid][d] = val;
    }
    __syncthreads();
    if (tid < 16) {
        float x = 0.f;
        for (int q = 0; q < 16; q++) x += s_part[q][tid];
        g_rec[b*128 + h*16 + tid] = x;
    }
}

// ---------------- per-step FC + logits + Gumbel sampling ----------------
__global__ void k_sample(int t, const float* __restrict__ ov_p, const float* __restrict__ qvf_W,
                         const float* __restrict__ qvf_b, const int* __restrict__ adj) {
    int b = blockIdx.x;
    int tid = threadIdx.x, lane = tid & 31, wid = tid >> 5;  // 512 threads
    __shared__ float rec_sh[128], hc_sh[128], qvf_sh[128];
    __shared__ float logits_sh[512];
    __shared__ float s_v[16]; __shared__ int s_i[16];
    __shared__ float s_m[16], s_s[16];

    if (tid < 128) rec_sh[tid] = g_rec[b*128 + tid];
    __syncthreads();
    if (tid < 128) {                                   // hvec_c[u] = sum_{h,d} ov_p[h,d,u]*rec
        float a = 0.f;
        for (int i = 0; i < 128; i++) a = fmaf(ov_p[i*128 + tid], rec_sh[i], a);
        hc_sh[tid] = a;
    }
    __syncthreads();
    if (tid < 128) {                                   // qvf = hvec_c @ W^T + b
        float a = 0.f;
        for (int v = 0; v < 128; v++) a = fmaf(qvf_W[tid*128 + v], hc_sh[v], a);
        qvf_sh[tid] = a + qvf_b[tid];
    }
    __syncthreads();

    int n = tid;
    float acc = 0.f;
    int base = b*128*N_ + n;
    for (int u = 0; u < 128; u++) acc = fmaf(qvf_sh[u], g_kvf[base + u*N_], acc);
    const float SQRTU = 11.3137084989847603904f;
    float cf = 10.0f * xla_tanhf(__fdiv_rn(acc, SQRTU));
    int last  = g_route[t*B_ + b];
    int check = g_check[b];
    bool adj_ok = adj[last*N_ + n] != 0;
    bool dem_ok = (n == 0) ? (check != 0) : (check == 0);
    float lg = adj_ok ? (dem_ok ? cf : -1e10f) : -1e30f;
    logits_sh[n] = lg;

    // JAX random bits (PARTITIONABLE mode): per-element 64-bit counter
    // (hi=0, lo=f); 32-bit output = bits1 ^ bits2.
    int f = b*N_ + n;
    unsigned x0 = 0u, x1 = (unsigned)f;
    tf2x32(g_keys[2*t], g_keys[2*t+1], x0, x1);
    unsigned bits = x0 ^ x1;
    float u0 = __uint_as_float((bits >> 9) | 0x3f800000u) - 1.0f;
    const float TINY = 1.17549435082228751e-38f;
    float uu = fmaxf(TINY, u0 + TINY);
    float g1 = -logf_hi(-logf_hi(uu));
    float val = lg + g1;

    // argmax(val) with first-index tie-break (JAX semantics)
    float bv = val; int bi = n;
#pragma unroll
    for (int o = 16; o > 0; o >>= 1) {
        float ov = __shfl_down_sync(0xffffffffu, bv, o);
        int   oi = __shfl_down_sync(0xffffffffu, bi, o);
        if (ov > bv || (ov == bv && oi < bi)) { bv = ov; bi = oi; }
    }
    if (lane == 0) { s_v[wid] = bv; s_i[wid] = bi; }

    // row max of logits (for log_softmax)
    float mv = lg;
    for (int o = 16; o > 0; o >>= 1) mv = fmaxf(mv, __shfl_down_sync(0xffffffffu, mv, o));
    if (lane == 0) s_m[wid] = mv;
    __syncthreads();

    __shared__ float s_gmx;
    if (tid == 0) { float x = s_m[0]; for (int i = 1; i < 16; i++) x = fmaxf(x, s_m[i]); s_gmx = x; }
    __syncthreads();
    float gmx = s_gmx;
    float ee = expf_hi(lg - gmx);
    float se = ee;
    for (int o = 16; o > 0; o >>= 1) se += __shfl_down_sync(0xffffffffu, se, o);
    if (lane == 0) s_s[wid] = se;
    __syncthreads();

    if (tid == 0) {
        float bbv = s_v[0]; int bbi = s_i[0];
        for (int i = 1; i < 16; i++) {
            if (s_v[i] > bbv || (s_v[i] == bbv && s_i[i] < bbi)) { bbv = s_v[i]; bbi = s_i[i]; }
        }
        float sum = 0.f;
        for (int i = 0; i < 16; i++) sum += s_s[i];
        g_target[b] = bbi;
        g_logprob[b] = (logits_sh[bbi] - gmx) - logf_hi(sum);
    }
}

// ---------------- per-step stats / route / done update ----------------
__global__ void k_stats(int t, const int* __restrict__ obj, const int* __restrict__ hml) {
    int b = threadIdx.x;  // 128 threads, 1 block
    __shared__ float red[128];
    int done = g_done;
    int tg = done ? 0 : g_target[b];
    g_route[(t+1)*B_ + b] = tg;
    int az = __syncthreads_and(tg == 0);
    int nd = (done || az) ? 1 : 0;
    if (!nd) {
        g_flp[b] += g_logprob[b];
        g_len[b] += (tg != 0) ? 1.f : 0.f;
    }
    // update demand-match mask with obj_list[tg]
    unsigned mk = g_matched[b];
    for (int m = 0; m < 16; m++) {
        int hv = hml[b*16 + m]; int mt = 0;
        for (int k = 0; k < 4; k++) mt |= (obj[tg*4 + k] == hv);
        if (mt) mk |= (1u << m);
    }
    g_matched[b] = mk;
    g_check[b] = (mk == 0xFFFFu) ? 1 : 0;

    red[b] = g_flp[b] * g_len[b];
    __syncthreads();
    for (int s = 64; s > 0; s >>= 1) {
        if (b < s) red[b] += red[b + s];
        __syncthreads();
    }
    if (b == 0) {
        if (!nd) g_loss = red[0] * (1.0f / 128.0f);
        g_done = nd;
    }
}

// ---------------- output: concat (route, loss, flp) as float32 ----------------
__global__ void k_out(float* __restrict__ out, int out_size) {
    int i = blockIdx.x * blockDim.x + threadIdx.x;
    if (i >= out_size) return;
    const int R = (MSTEPS+1)*B_;  // 9088
    if (i < R)               out[i] = (float)g_route[i];
    else if (i == R)         out[i] = g_loss;
    else if (i < R + 1 + B_) out[i] = g_flp[i - R - 1];
    else                     out[i] = 0.f;
}

extern "C" void kernel_launch(void* const* d_in, const int* in_sizes, int n_in,
                              void* d_out, int out_size) {
    const float* hvec  = (const float*)d_in[0];
    const float* hbar  = (const float*)d_in[1];
    const int*   adj   = (const int*)  d_in[2];
    const int*   obj   = (const int*)  d_in[3];
    const int*   hml   = (const int*)  d_in[4];
    const float* qv_p  = (const float*)d_in[5];
    const float* kv_p  = (const float*)d_in[6];
    const float* vv_p  = (const float*)d_in[7];
    const float* ov_p  = (const float*)d_in[8];
    const float* qvf_W = (const float*)d_in[9];
    const float* qvf_b = (const float*)d_in[10];
    const float* kvf_W = (const float*)d_in[11];
    const float* kvf_b = (const float*)d_in[12];
    const float* vec_1 = (const float*)d_in[13];
    const float* vec_f = (const float*)d_in[14];
    float* out = (float*)d_out;

    k_init<<<1, 128>>>(obj, hml);
    k_prep_kv<<<dim3(64, 128), 128>>>(hvec, kv_p, vv_p);
    k_prep_kvf<<<dim3(64, 128), 128>>>(hvec, kvf_W, kvf_b);

    for (int t = 0; t < MSTEPS; t++) {
        k_att<<<dim3(8, 128), 512>>>(t, hvec, hbar, qv_p, adj, vec_1, vec_f);
        k_sample<<<128, 512>>>(t, ov_p, qvf_W, qvf_b, adj);
        k_stats<<<1, 128>>>(t, obj, hml);
    }

    int total = out_size;
    int blocks = (total + 127) / 128;
    if (blocks < 1) blocks = 1;
    k_out<<<blocks, 128>>>(out, out_size);
}

// round 9
// speedup vs baseline: 1.3557x; 1.3557x over previous
#include <cuda_runtime.h>
#include <math.h>

#define B_ 128
#define N_ 512
#define U_ 128
#define MSTEPS 70

// ---------------- device scratch ----------------
__device__ float g_kv [B_*128*N_];     // [b][h*16+d][n]  (streamed, evict_first)
__device__ float g_vv [B_*128*N_];     // [b][h*16+d][n]  (resident, evict_last)
__device__ float g_kvf[B_*U_*N_];      // [b][u][n]       (resident, evict_last)
__device__ float g_gum[MSTEPS*65536];  // precomputed gumbel noise [t][b*512+n]
__device__ int   g_route[(MSTEPS+1)*B_];
__device__ float g_flp[B_];
__device__ float g_len[B_];
__device__ int   g_doneA[2];
__device__ unsigned g_matched[B_];
__device__ int   g_check[B_];
__device__ int   g_targetA[2][B_];     // double-buffered raw sampled targets
__device__ float g_logprob[B_];
__device__ unsigned g_keys[MSTEPS*2];

// ---------------- Threefry-2x32-20 (JAX partitionable) ----------------
__device__ __forceinline__ void tf2x32(unsigned k0, unsigned k1, unsigned &x0, unsigned &x1) {
    unsigned ks2 = k0 ^ k1 ^ 0x1BD11BDAu;
    x0 += k0; x1 += k1;
#define TFR(r) { x0 += x1; x1 = (x1<<(r)) | (x1>>(32-(r))); x1 ^= x0; }
    TFR(13) TFR(15) TFR(26) TFR(6)
    x0 += k1;  x1 += ks2 + 1u;
    TFR(17) TFR(29) TFR(16) TFR(24)
    x0 += ks2; x1 += k0 + 2u;
    TFR(13) TFR(15) TFR(26) TFR(6)
    x0 += k0;  x1 += k1 + 3u;
    TFR(17) TFR(29) TFR(16) TFR(24)
    x0 += k1;  x1 += ks2 + 4u;
    TFR(13) TFR(15) TFR(26) TFR(6)
    x0 += ks2; x1 += k0 + 5u;
#undef TFR
}

// ---------------- accurate f32 transcendentals (fast-math immune) ----------------
__device__ __forceinline__ float expf_acc(float x) {
    if (x < -87.0f) return 0.f;                 // our args are <= 0
    float k = rintf(x * 1.4426950408889634f);
    float r = fmaf(k, -0.693359375f, x);
    r = fmaf(k, 2.12194440e-4f, r);
    float z = r * r;
    float p = 1.9875691500e-4f;
    p = fmaf(p, r, 1.3981999507e-3f);
    p = fmaf(p, r, 8.3334519073e-3f);
    p = fmaf(p, r, 4.1665795894e-2f);
    p = fmaf(p, r, 1.6666665459e-1f);
    p = fmaf(p, r, 5.0000001201e-1f);
    float res = fmaf(z, p, r) + 1.0f;
    int ki = (int)k;
    return res * __int_as_float((ki + 127) << 23);
}

__device__ __forceinline__ float logf_acc(float x) {
    int hx = __float_as_int(x);
    int k = ((hx >> 23) & 0xff) - 127;
    hx = (hx & 0x7fffff) | 0x3f800000;
    float m = __int_as_float(hx);
    if (m >= 1.41421356237f) { m *= 0.5f; k++; }
    float f = m - 1.0f;                          // exact
    float s = __fdiv_rn(f, 2.0f + f);
    float z = s * s;
    float w = z * z;
    float t1 = w * fmaf(w, 0.24279078841f, 0.40000972152f);
    float t2 = z * fmaf(w, 0.28498786688f, 0.66666662693f);
    float R = t2 + t1;
    float hfsq = 0.5f * f * f;
    float dk = (float)k;
    float r = fmaf(s, hfsq + R, dk * 9.0580006145e-06f);
    return dk * 0.69313812256f - ((hfsq - r) - f);
}

// ---------------- XLA fast-tanh ----------------
__device__ __forceinline__ float xla_tanhf(float x) {
    float ax = fabsf(x);
    const float cl = 7.90531110763549805f;
    float xc = fminf(fmaxf(x, -cl), cl);
    float x2 = xc * xc;
    float p = fmaf(x2, -2.76076847742355e-16f, 2.00018790482477e-13f);
    p = fmaf(x2, p, -8.60467152213735e-11f);
    p = fmaf(x2, p,  5.12229709037114e-08f);
    p = fmaf(x2, p,  1.48572235717979e-05f);
    p = fmaf(x2, p,  6.37261928875436e-04f);
    p = fmaf(x2, p,  4.89352455891786e-03f);
    p = p * xc;
    float q = fmaf(x2, 1.19825839466702e-06f, 1.18534705686654e-04f);
    q = fmaf(x2, q, 2.26843463243900e-03f);
    q = fmaf(x2, q, 4.89352518554385e-03f);
    float r = __fdiv_rn(p, q);
    return (ax < 0.0004f) ? x : r;
}

// ---------------- L2 policy loads (createpolicy + cache_hint form) ----------------
__device__ __forceinline__ unsigned long long pol_evict_last() {
    unsigned long long p;
    asm("createpolicy.fractional.L2::evict_last.b64 %0, 1.0;" : "=l"(p));
    return p;
}
__device__ __forceinline__ unsigned long long pol_evict_first() {
    unsigned long long p;
    asm("createpolicy.fractional.L2::evict_first.b64 %0, 1.0;" : "=l"(p));
    return p;
}
__device__ __forceinline__ float ldg_hint(const float* p, unsigned long long pol) {
    float v;
    asm("ld.global.nc.L2::cache_hint.f32 %0,[%1],%2;" : "=f"(v) : "l"(p), "l"(pol));
    return v;
}

// ---------------- init ----------------
__global__ void k_init(const int* __restrict__ obj, const int* __restrict__ hml) {
    int b = threadIdx.x;  // 128 threads
    for (int i = b; i < (MSTEPS+1)*B_; i += B_) g_route[i] = 0;
    g_flp[b] = 0.f; g_len[b] = 0.f;
    if (b == 0) { g_doneA[0] = 0; g_doneA[1] = 0; }
    if (b < MSTEPS) {  // partitionable split
        unsigned x0 = 0u, x1 = (unsigned)b;
        tf2x32(0u, 42u, x0, x1);
        g_keys[2*b] = x0; g_keys[2*b+1] = x1;
    }
    int lz = 0;
    for (int m = 0; m < 16; m++) lz |= (hml[b*16 + m] == 0);
    int hz = __syncthreads_or(lz);
    unsigned mk = 0;
    for (int m = 0; m < 16; m++) {
        int v = hml[b*16 + m]; int mt = 0;
        for (int k = 0; k < 4; k++) mt |= (obj[k] == v);
        if (mt) mk |= (1u << m);
    }
    if (hz) mk |= 1u;
    g_matched[b] = mk;
    g_check[b] = (mk == 0xFFFFu) ? 1 : 0;
}

// ---------------- precompute gumbel noise ----------------
__global__ void k_gum() {
    int idx = blockIdx.x * 512 + threadIdx.x;   // 70*65536 total
    int t = idx >> 16, f = idx & 65535;
    unsigned x0 = 0u, x1 = (unsigned)f;
    tf2x32(g_keys[2*t], g_keys[2*t+1], x0, x1);
    unsigned bits = x0 ^ x1;
    float u0 = __uint_as_float((bits >> 9) | 0x3f800000u) - 1.0f;
    const float TINY = 1.17549435082228751e-38f;
    float uu = fmaxf(TINY, u0 + TINY);
    g_gum[idx] = -logf_acc(-logf_acc(uu));
}

// ---------------- precompute kv, vv ----------------
__global__ void k_prep_kv(const float* __restrict__ hvec, const float* __restrict__ kv_p,
                          const float* __restrict__ vv_p) {
    int b = blockIdx.y, n0 = blockIdx.x * 8;
    int t = threadIdx.x;
    __shared__ float hs[8*128];
    for (int i = t; i < 8*128; i += 128)
        hs[i] = hvec[(b*N_ + n0 + (i >> 7))*U_ + (i & 127)];
    __syncthreads();
    float ak[8], av[8];
#pragma unroll
    for (int j = 0; j < 8; j++) { ak[j] = 0.f; av[j] = 0.f; }
    for (int x = 0; x < 128; x++) {
        float kp = kv_p[x*128 + t];
        float vp = vv_p[x*128 + t];
#pragma unroll
        for (int j = 0; j < 8; j++) {
            float hx = hs[j*128 + x];
            ak[j] = fmaf(kp, hx, ak[j]);
            av[j] = fmaf(vp, hx, av[j]);
        }
    }
#pragma unroll
    for (int j = 0; j < 8; j++) {
        g_kv[(b*128 + t)*N_ + n0 + j] = ak[j];
        g_vv[(b*128 + t)*N_ + n0 + j] = av[j];
    }
}

// ---------------- precompute kvf ----------------
__global__ void k_prep_kvf(const float* __restrict__ hvec, const float* __restrict__ W,
                           const float* __restrict__ bias) {
    int b = blockIdx.y, n0 = blockIdx.x * 8;
    int u = threadIdx.x;
    __shared__ float hs[8*128];
    for (int i = u; i < 8*128; i += 128)
        hs[i] = hvec[(b*N_ + n0 + (i >> 7))*U_ + (i & 127)];
    __syncthreads();
    float a[8];
#pragma unroll
    for (int j = 0; j < 8; j++) a[j] = 0.f;
    for (int v = 0; v < 128; v++) {
        float w = W[u*128 + v];
#pragma unroll
        for (int j = 0; j < 8; j++) a[j] = fmaf(w, hs[j*128 + v], a[j]);
    }
    float bb = bias[u];
#pragma unroll
    for (int j = 0; j < 8; j++) g_kvf[(b*128 + u)*N_ + n0 + j] = a[j] + bb;
}

// ---------------- fused per-step kernel: stats(prev) + attention + FC + sample ----------------
__global__ void __launch_bounds__(1024, 1)
k_step(int t, const float* __restrict__ hvec, const float* __restrict__ hbar,
       const float* __restrict__ qv_p, const int* __restrict__ adj,
       const float* __restrict__ vec_1, const float* __restrict__ vec_f,
       const float* __restrict__ ov_p, const float* __restrict__ qvf_W,
       const float* __restrict__ qvf_b, const int* __restrict__ obj,
       const int* __restrict__ hml) {
    int b = blockIdx.x;
    int tid = threadIdx.x;
    int half = tid >> 9;        // 0 or 1
    int hn   = tid & 511;       // n within half
    int lane = tid & 31;
    int wid  = tid >> 5;        // 0..31
    int hwid = wid & 15;        // warp within half

    __shared__ float c_sh[384];
    __shared__ float qv_sh[128];
    __shared__ float s_red[2][16];
    __shared__ float s_b0[2], s_b1[2];
    __shared__ float s_part[2][16][17];
    __shared__ float rec_sh[128];
    __shared__ float hc_sh[128];
    __shared__ float qvf_sh[128];
    __shared__ float logits_sh[512];
    __shared__ float s_v[16]; __shared__ int s_i[16];
    __shared__ float s_m[16], s_s[16];
    __shared__ float s_gmx;
    __shared__ int s_last, s_check, s_done;
    __shared__ int s_t[128];

    unsigned long long PEL = pol_evict_last();
    unsigned long long PEF = pol_evict_first();

    // ---- phase 0: apply previous step's sampled targets (stats) ----
    if (t == 0) {
        if (tid == 0) { s_last = 0; s_check = g_check[b]; s_done = 0; }
    } else {
        if (tid < 128) s_t[tid] = g_targetA[(t-1) & 1][tid];
        __syncthreads();
        if (tid == 0) {
            int done_prev = g_doneA[(t-1) & 1];
            int a = 1;
            for (int i = 0; i < 128; i++) a &= (s_t[i] == 0);
            int done_t = (done_prev || a) ? 1 : 0;
            int tg = done_prev ? 0 : s_t[b];
            g_route[t*B_ + b] = tg;
            if (!done_t) {
                g_flp[b] += g_logprob[b];
                g_len[b] += (tg != 0) ? 1.f : 0.f;
            }
            unsigned mk = g_matched[b];
#pragma unroll
            for (int m = 0; m < 16; m++) {
                int hv = hml[b*16 + m]; int mt = 0;
#pragma unroll
                for (int k2 = 0; k2 < 4; k2++) mt |= (obj[tg*4 + k2] == hv);
                if (mt) mk |= (1u << m);
            }
            g_matched[b] = mk;
            s_last = tg; s_check = (mk == 0xFFFFu) ? 1 : 0; s_done = done_t;
            if (b == 0) g_doneA[t & 1] = done_t;
        }
    }
    __syncthreads();
    if (s_done) return;

    // ---- context vector [hbar | prev_vec | first_vec] ----
    if (tid < 384) {
        float v;
        if (t == 0) {
            v = (tid < 128) ? hbar[tid]
              : (tid < 256) ? vec_1[b*U_ + tid - 128]
                            : vec_f[b*U_ + tid - 256];
        } else {
            int previ  = g_route[(t-1)*B_ + b];
            int firsti = (t == 1) ? s_last : g_route[B_ + b];
            v = (tid < 128) ? hbar[tid]
              : (tid < 256) ? hvec[(b*N_ + previ)*U_ + tid - 128]
                            : hvec[(b*N_ + firsti)*U_ + tid - 256];
        }
        c_sh[tid] = v;
    }
    __syncthreads();

    // ---- qv: warp hwid computes d=hwid for this half's 4 heads (same order as R6) ----
    {
        int d = hwid;
        for (int hh = 0; hh < 4; hh++) {
            int h = half*4 + hh;
            float acc = 0.f;
            for (int x = lane; x < 384; x += 32)
                acc = fmaf(qv_p[x*128 + h*16 + d], c_sh[x], acc);
            for (int o = 16; o > 0; o >>= 1) acc += __shfl_down_sync(0xffffffffu, acc, o);
            if (lane == 0) qv_sh[h*16 + d] = acc;
        }
    }
    __syncthreads();

    // ---- attention: each half handles 4 heads over n=hn ----
    const int n = hn;
    const int adjv = adj[s_last*N_ + n];
    const bool adj_ok = adjv != 0;
    const bool dem_ok = (n == 0) ? (s_check != 0) : (s_check == 0);

    for (int hh = 0; hh < 4; hh++) {
        int h = half*4 + hh;
        int base = (b*128 + h*16)*N_ + n;
        float acc = 0.f;
#pragma unroll
        for (int d = 0; d < 16; d++) acc = fmaf(qv_sh[h*16 + d], ldg_hint(&g_kv[base + d*N_], PEF), acc);
        float m = adj_ok ? (dem_ok ? acc*0.25f : -1e10f) : -1e30f;

        float v = m;
        for (int o = 16; o > 0; o >>= 1) v = fmaxf(v, __shfl_down_sync(0xffffffffu, v, o));
        if (lane == 0) s_red[half][hwid] = v;
        __syncthreads();
        if (hn == 0) { float x = s_red[half][0]; for (int i = 1; i < 16; i++) x = fmaxf(x, s_red[half][i]); s_b0[half] = x; }
        __syncthreads();
        float e = expf_acc(m - s_b0[half]);
        float sv = e;
        for (int o = 16; o > 0; o >>= 1) sv += __shfl_down_sync(0xffffffffu, sv, o);
        if (lane == 0) s_red[half][hwid] = sv;
        __syncthreads();
        if (hn == 0) { float x = 0.f; for (int i = 0; i < 16; i++) x += s_red[half][i]; s_b1[half] = x; }
        __syncthreads();
        float w = __fdiv_rn(e, s_b1[half]);

#pragma unroll
        for (int d = 0; d < 16; d++) {
            float val = w * ldg_hint(&g_vv[base + d*N_], PEL);
            for (int o = 16; o > 0; o >>= 1) val += __shfl_down_sync(0xffffffffu, val, o);
            if (lane == 0) s_part[half][hwid][d] = val;
        }
        __syncthreads();
        if (hn < 16) {
            float x = 0.f;
            for (int q = 0; q < 16; q++) x += s_part[half][q][hn];
            rec_sh[h*16 + hn] = x;
        }
        __syncthreads();
    }

    // ---- FC: hvec_c, qvf (same serial orders as R6) ----
    if (tid < 128) {
        float a = 0.f;
        for (int i = 0; i < 128; i++) a = fmaf(ov_p[i*128 + tid], rec_sh[i], a);
        hc_sh[tid] = a;
    }
    __syncthreads();
    if (tid < 128) {
        float a = 0.f;
        for (int v = 0; v < 128; v++) a = fmaf(qvf_W[tid*128 + v], hc_sh[v], a);
        qvf_sh[tid] = a + qvf_b[tid];
    }
    __syncthreads();

    // ---- logits + gumbel sample (threads < 512) ----
    float lg = 0.f;
    if (tid < 512) {
        float acc = 0.f;
        int base = b*128*N_ + n;
        for (int u = 0; u < 128; u++) acc = fmaf(qvf_sh[u], ldg_hint(&g_kvf[base + u*N_], PEL), acc);
        const float SQRTU = 11.3137084989847603904f;
        float cf = 10.0f * xla_tanhf(__fdiv_rn(acc, SQRTU));
        lg = adj_ok ? (dem_ok ? cf : -1e10f) : -1e30f;
        logits_sh[n] = lg;
        float g1 = ldg_hint(&g_gum[t*65536 + b*512 + n], PEF);
        float val = lg + g1;

        float bv = val; int bi = n;
#pragma unroll
        for (int o = 16; o > 0; o >>= 1) {
            float ov = __shfl_down_sync(0xffffffffu, bv, o);
            int   oi = __shfl_down_sync(0xffffffffu, bi, o);
            if (ov > bv || (ov == bv && oi < bi)) { bv = ov; bi = oi; }
        }
        float mv = lg;
        for (int o = 16; o > 0; o >>= 1) mv = fmaxf(mv, __shfl_down_sync(0xffffffffu, mv, o));
        if (lane == 0) { s_v[wid] = bv; s_i[wid] = bi; s_m[wid] = mv; }
    }
    __syncthreads();
    if (tid == 0) { float x = s_m[0]; for (int i = 1; i < 16; i++) x = fmaxf(x, s_m[i]); s_gmx = x; }
    __syncthreads();
    if (tid < 512) {
        float ee = expf_acc(lg - s_gmx);
        for (int o = 16; o > 0; o >>= 1) ee += __shfl_down_sync(0xffffffffu, ee, o);
        if (lane == 0) s_s[wid] = ee;
    }
    __syncthreads();
    if (tid == 0) {
        float bbv = s_v[0]; int bbi = s_i[0];
        for (int i = 1; i < 16; i++) {
            if (s_v[i] > bbv || (s_v[i] == bbv && s_i[i] < bbi)) { bbv = s_v[i]; bbi = s_i[i]; }
        }
        float sum = 0.f;
        for (int i = 0; i < 16; i++) sum += s_s[i];
        g_targetA[t & 1][b] = bbi;
        g_logprob[b] = (logits_sh[bbi] - s_gmx) - logf_acc(sum);
    }
}

// ---------------- finalize + output ----------------
__global__ void k_out(float* __restrict__ out, int out_size) {
    int b = threadIdx.x;  // 128 threads, 1 block
    __shared__ float red[128];
    __shared__ int s_t[128];
    __shared__ int s_az;
    s_t[b] = g_targetA[(MSTEPS-1) & 1][b];
    __syncthreads();
    if (b == 0) { int a = 1; for (int i = 0; i < 128; i++) a &= (s_t[i] == 0); s_az = a; }
    __syncthreads();
    int done_prev = g_doneA[(MSTEPS-1) & 1];
    int done_t = (done_prev || s_az) ? 1 : 0;
    int tg = done_prev ? 0 : s_t[b];
    g_route[MSTEPS*B_ + b] = tg;
    if (!done_t) {
        g_flp[b] += g_logprob[b];
        g_len[b] += (tg != 0) ? 1.f : 0.f;
    }
    red[b] = g_flp[b] * g_len[b];
    __syncthreads();
    for (int s = 64; s > 0; s >>= 1) {
        if (b < s) red[b] += red[b + s];
        __syncthreads();
    }
    float loss = red[0] * (1.0f / 128.0f);
    __syncthreads();
    const int R = (MSTEPS+1)*B_;  // 9088
    for (int i = b; i < out_size; i += 128) {
        float v;
        if (i < R)               v = (float)g_route[i];
        else if (i == R)         v = loss;
        else if (i < R + 1 + B_) v = g_flp[i - R - 1];
        else                     v = 0.f;
        out[i] = v;
    }
}

extern "C" void kernel_launch(void* const* d_in, const int* in_sizes, int n_in,
                              void* d_out, int out_size) {
    const float* hvec  = (const float*)d_in[0];
    const float* hbar  = (const float*)d_in[1];
    const int*   adj   = (const int*)  d_in[2];
    const int*   obj   = (const int*)  d_in[3];
    const int*   hml   = (const int*)  d_in[4];
    const float* qv_p  = (const float*)d_in[5];
    const float* kv_p  = (const float*)d_in[6];
    const float* vv_p  = (const float*)d_in[7];
    const float* ov_p  = (const float*)d_in[8];
    const float* qvf_W = (const float*)d_in[9];
    const float* qvf_b = (const float*)d_in[10];
    const float* kvf_W = (const float*)d_in[11];
    const float* kvf_b = (const float*)d_in[12];
    const float* vec_1 = (const float*)d_in[13];
    const float* vec_f = (const float*)d_in[14];
    float* out = (float*)d_out;

    k_init<<<1, 128>>>(obj, hml);
    k_gum<<<(MSTEPS*65536)/512, 512>>>();
    k_prep_kv<<<dim3(64, 128), 128>>>(hvec, kv_p, vv_p);
    k_prep_kvf<<<dim3(64, 128), 128>>>(hvec, kvf_W, kvf_b);

    for (int t = 0; t < MSTEPS; t++) {
        k_step<<<128, 1024>>>(t, hvec, hbar, qv_p, adj, vec_1, vec_f,
                              ov_p, qvf_W, qvf_b, obj, hml);
    }
    k_out<<<1, 128>>>(out, out_size);
}

// round 10
// speedup vs baseline: 1.9135x; 1.4115x over previous
#include <cuda_runtime.h>
#include <math.h>

#define B_ 128
#define N_ 512
#define U_ 128
#define MSTEPS 70

// ---------------- device scratch ----------------
__device__ float g_kv [B_*128*N_];     // [b][h*16+d][n]  (streamed, evict_first)
__device__ float g_vv [B_*128*N_];     // [b][h*16+d][n]  (resident, evict_last)
__device__ float g_kvf[B_*U_*N_];      // [b][u][n]       (resident, evict_last)
__device__ float g_gum[MSTEPS*65536];  // precomputed gumbel noise [t][b*512+n]
__device__ float g_WTkvf[U_*U_];       // kvf_W transposed: [v][u]
__device__ float g_WTqvf[U_*U_];       // qvf_W transposed: [v][u]
__device__ int   g_route[(MSTEPS+1)*B_];
__device__ float g_flp[B_];
__device__ float g_len[B_];
__device__ int   g_doneA[2];
__device__ unsigned g_matched[B_];
__device__ int   g_check[B_];
__device__ int   g_targetA[2][B_];
__device__ float g_logprob[B_];
__device__ unsigned g_keys[MSTEPS*2];

// ---------------- Threefry-2x32-20 (JAX partitionable) ----------------
__device__ __forceinline__ void tf2x32(unsigned k0, unsigned k1, unsigned &x0, unsigned &x1) {
    unsigned ks2 = k0 ^ k1 ^ 0x1BD11BDAu;
    x0 += k0; x1 += k1;
#define TFR(r) { x0 += x1; x1 = (x1<<(r)) | (x1>>(32-(r))); x1 ^= x0; }
    TFR(13) TFR(15) TFR(26) TFR(6)
    x0 += k1;  x1 += ks2 + 1u;
    TFR(17) TFR(29) TFR(16) TFR(24)
    x0 += ks2; x1 += k0 + 2u;
    TFR(13) TFR(15) TFR(26) TFR(6)
    x0 += k0;  x1 += k1 + 3u;
    TFR(17) TFR(29) TFR(16) TFR(24)
    x0 += k1;  x1 += ks2 + 4u;
    TFR(13) TFR(15) TFR(26) TFR(6)
    x0 += ks2; x1 += k0 + 5u;
#undef TFR
}

// ---------------- accurate f32 transcendentals (fast-math immune) ----------------
__device__ __forceinline__ float expf_acc(float x) {
    if (x < -87.0f) return 0.f;
    float k = rintf(x * 1.4426950408889634f);
    float r = fmaf(k, -0.693359375f, x);
    r = fmaf(k, 2.12194440e-4f, r);
    float z = r * r;
    float p = 1.9875691500e-4f;
    p = fmaf(p, r, 1.3981999507e-3f);
    p = fmaf(p, r, 8.3334519073e-3f);
    p = fmaf(p, r, 4.1665795894e-2f);
    p = fmaf(p, r, 1.6666665459e-1f);
    p = fmaf(p, r, 5.0000001201e-1f);
    float res = fmaf(z, p, r) + 1.0f;
    int ki = (int)k;
    return res * __int_as_float((ki + 127) << 23);
}

__device__ __forceinline__ float logf_acc(float x) {
    int hx = __float_as_int(x);
    int k = ((hx >> 23) & 0xff) - 127;
    hx = (hx & 0x7fffff) | 0x3f800000;
    float m = __int_as_float(hx);
    if (m >= 1.41421356237f) { m *= 0.5f; k++; }
    float f = m - 1.0f;
    float s = __fdiv_rn(f, 2.0f + f);
    float z = s * s;
    float w = z * z;
    float t1 = w * fmaf(w, 0.24279078841f, 0.40000972152f);
    float t2 = z * fmaf(w, 0.28498786688f, 0.66666662693f);
    float R = t2 + t1;
    float hfsq = 0.5f * f * f;
    float dk = (float)k;
    float r = fmaf(s, hfsq + R, dk * 9.0580006145e-06f);
    return dk * 0.69313812256f - ((hfsq - r) - f);
}

// ---------------- XLA fast-tanh ----------------
__device__ __forceinline__ float xla_tanhf(float x) {
    float ax = fabsf(x);
    const float cl = 7.90531110763549805f;
    float xc = fminf(fmaxf(x, -cl), cl);
    float x2 = xc * xc;
    float p = fmaf(x2, -2.76076847742355e-16f, 2.00018790482477e-13f);
    p = fmaf(x2, p, -8.60467152213735e-11f);
    p = fmaf(x2, p,  5.12229709037114e-08f);
    p = fmaf(x2, p,  1.48572235717979e-05f);
    p = fmaf(x2, p,  6.37261928875436e-04f);
    p = fmaf(x2, p,  4.89352455891786e-03f);
    p = p * xc;
    float q = fmaf(x2, 1.19825839466702e-06f, 1.18534705686654e-04f);
    q = fmaf(x2, q, 2.26843463243900e-03f);
    q = fmaf(x2, q, 4.89352518554385e-03f);
    float r = __fdiv_rn(p, q);
    return (ax < 0.0004f) ? x : r;
}

// ---------------- L2 policy loads ----------------
__device__ __forceinline__ unsigned long long pol_evict_last() {
    unsigned long long p;
    asm("createpolicy.fractional.L2::evict_last.b64 %0, 1.0;" : "=l"(p));
    return p;
}
__device__ __forceinline__ unsigned long long pol_evict_first() {
    unsigned long long p;
    asm("createpolicy.fractional.L2::evict_first.b64 %0, 1.0;" : "=l"(p));
    return p;
}
__device__ __forceinline__ float ldg_hint(const float* p, unsigned long long pol) {
    float v;
    asm("ld.global.nc.L2::cache_hint.f32 %0,[%1],%2;" : "=f"(v) : "l"(p), "l"(pol));
    return v;
}

// ---------------- init ----------------
__global__ void k_init(const int* __restrict__ obj, const int* __restrict__ hml) {
    int b = threadIdx.x;  // 128 threads
    for (int i = b; i < (MSTEPS+1)*B_; i += B_) g_route[i] = 0;
    g_flp[b] = 0.f; g_len[b] = 0.f;
    if (b == 0) { g_doneA[0] = 0; g_doneA[1] = 0; }
    if (b < MSTEPS) {
        unsigned x0 = 0u, x1 = (unsigned)b;
        tf2x32(0u, 42u, x0, x1);
        g_keys[2*b] = x0; g_keys[2*b+1] = x1;
    }
    int lz = 0;
    for (int m = 0; m < 16; m++) lz |= (hml[b*16 + m] == 0);
    int hz = __syncthreads_or(lz);
    unsigned mk = 0;
    for (int m = 0; m < 16; m++) {
        int v = hml[b*16 + m]; int mt = 0;
        for (int k = 0; k < 4; k++) mt |= (obj[k] == v);
        if (mt) mk |= (1u << m);
    }
    if (hz) mk |= 1u;
    g_matched[b] = mk;
    g_check[b] = (mk == 0xFFFFu) ? 1 : 0;
}

// ---------------- transpose FC weights (runs once) ----------------
__global__ void k_tw(const float* __restrict__ kvfW, const float* __restrict__ qvfW) {
    int i = blockIdx.x * 256 + threadIdx.x;   // 16384 total
    int u = i >> 7, v = i & 127;
    g_WTkvf[v*128 + u] = kvfW[i];
    g_WTqvf[v*128 + u] = qvfW[i];
}

// ---------------- precompute gumbel noise ----------------
__global__ void k_gum() {
    int idx = blockIdx.x * 512 + threadIdx.x;   // 70*65536 total
    int t = idx >> 16, f = idx & 65535;
    unsigned x0 = 0u, x1 = (unsigned)f;
    tf2x32(g_keys[2*t], g_keys[2*t+1], x0, x1);
    unsigned bits = x0 ^ x1;
    float u0 = __uint_as_float((bits >> 9) | 0x3f800000u) - 1.0f;
    const float TINY = 1.17549435082228751e-38f;
    float uu = fmaxf(TINY, u0 + TINY);
    g_gum[idx] = -logf_acc(-logf_acc(uu));
}

// ---------------- precompute kv, vv ----------------
__global__ void k_prep_kv(const float* __restrict__ hvec, const float* __restrict__ kv_p,
                          const float* __restrict__ vv_p) {
    int b = blockIdx.y, n0 = blockIdx.x * 8;
    int t = threadIdx.x;
    __shared__ float hs[8*128];
    for (int i = t; i < 8*128; i += 128)
        hs[i] = hvec[(b*N_ + n0 + (i >> 7))*U_ + (i & 127)];
    __syncthreads();
    float ak[8], av[8];
#pragma unroll
    for (int j = 0; j < 8; j++) { ak[j] = 0.f; av[j] = 0.f; }
    for (int x = 0; x < 128; x++) {
        float kp = kv_p[x*128 + t];
        float vp = vv_p[x*128 + t];
#pragma unroll
        for (int j = 0; j < 8; j++) {
            float hx = hs[j*128 + x];
            ak[j] = fmaf(kp, hx, ak[j]);
            av[j] = fmaf(vp, hx, av[j]);
        }
    }
#pragma unroll
    for (int j = 0; j < 8; j++) {
        g_kv[(b*128 + t)*N_ + n0 + j] = ak[j];
        g_vv[(b*128 + t)*N_ + n0 + j] = av[j];
    }
}

// ---------------- precompute kvf (coalesced via transposed W) ----------------
__global__ void k_prep_kvf(const float* __restrict__ hvec, const float* __restrict__ bias) {
    int b = blockIdx.y, n0 = blockIdx.x * 8;
    int u = threadIdx.x;
    __shared__ float hs[8*128];
    for (int i = u; i < 8*128; i += 128)
        hs[i] = hvec[(b*N_ + n0 + (i >> 7))*U_ + (i & 127)];
    __syncthreads();
    float a[8];
#pragma unroll
    for (int j = 0; j < 8; j++) a[j] = 0.f;
    for (int v = 0; v < 128; v++) {
        float w = g_WTkvf[v*128 + u];          // coalesced across u
#pragma unroll
        for (int j = 0; j < 8; j++) a[j] = fmaf(w, hs[j*128 + v], a[j]);
    }
    float bb = bias[u];
#pragma unroll
    for (int j = 0; j < 8; j++) g_kvf[(b*128 + u)*N_ + n0 + j] = a[j] + bb;
}

// ---------------- fused per-step kernel ----------------
__global__ void __launch_bounds__(1024, 1)
k_step(int t, const float* __restrict__ hvec, const float* __restrict__ hbar,
       const float* __restrict__ qv_p, const int* __restrict__ adj,
       const float* __restrict__ vec_1, const float* __restrict__ vec_f,
       const float* __restrict__ ov_p, const float* __restrict__ qvf_b,
       const int* __restrict__ obj, const int* __restrict__ hml) {
    int b = blockIdx.x;
    int tid = threadIdx.x;
    int half = tid >> 9;        // 0 or 1
    int hn   = tid & 511;       // n within half
    int lane = tid & 31;
    int wid  = tid >> 5;        // 0..31
    int hwid = wid & 15;        // warp within half

    __shared__ float c_sh[384];
    __shared__ float qv_sh[128];
    __shared__ float w_sh[8][512];
    __shared__ float s_redM[2][16][4];
    __shared__ float s_mx[8], s_sum[8];
    __shared__ float rec_sh[128];
    __shared__ float hc_sh[128];
    __shared__ float qvf_sh[128];
    __shared__ float logits_sh[512];
    __shared__ float s_v[16]; __shared__ int s_i[16];
    __shared__ float s_m[16], s_s[16];
    __shared__ float s_gmx;
    __shared__ int s_last, s_check, s_done;
    __shared__ int s_t[128];

    unsigned long long PEL = pol_evict_last();
    unsigned long long PEF = pol_evict_first();

    // ---- phase 0: apply previous step's sampled targets (stats) ----
    if (t == 0) {
        if (tid == 0) { s_last = 0; s_check = g_check[b]; s_done = 0; }
    } else {
        if (tid < 128) s_t[tid] = g_targetA[(t-1) & 1][tid];
        __syncthreads();
        if (tid == 0) {
            int done_prev = g_doneA[(t-1) & 1];
            int a = 1;
            for (int i = 0; i < 128; i++) a &= (s_t[i] == 0);
            int done_t = (done_prev || a) ? 1 : 0;
            int tg = done_prev ? 0 : s_t[b];
            g_route[t*B_ + b] = tg;
            if (!done_t) {
                g_flp[b] += g_logprob[b];
                g_len[b] += (tg != 0) ? 1.f : 0.f;
            }
            unsigned mk = g_matched[b];
#pragma unroll
            for (int m = 0; m < 16; m++) {
                int hv = hml[b*16 + m]; int mt = 0;
#pragma unroll
                for (int k2 = 0; k2 < 4; k2++) mt |= (obj[tg*4 + k2] == hv);
                if (mt) mk |= (1u << m);
            }
            g_matched[b] = mk;
            s_last = tg; s_check = (mk == 0xFFFFu) ? 1 : 0; s_done = done_t;
            if (b == 0) g_doneA[t & 1] = done_t;
        }
    }
    __syncthreads();
    if (s_done) return;

    // ---- context vector [hbar | prev_vec | first_vec] ----
    if (tid < 384) {
        float v;
        if (t == 0) {
            v = (tid < 128) ? hbar[tid]
              : (tid < 256) ? vec_1[b*U_ + tid - 128]
                            : vec_f[b*U_ + tid - 256];
        } else {
            int previ  = g_route[(t-1)*B_ + b];
            int firsti = (t == 1) ? s_last : g_route[B_ + b];
            v = (tid < 128) ? hbar[tid]
              : (tid < 256) ? hvec[(b*N_ + previ)*U_ + tid - 128]
                            : hvec[(b*N_ + firsti)*U_ + tid - 256];
        }
        c_sh[tid] = v;
    }
    __syncthreads();

    // ---- qv ----
    {
        int d = hwid;
        for (int hh = 0; hh < 4; hh++) {
            int h = half*4 + hh;
            float acc = 0.f;
            for (int x = lane; x < 384; x += 32)
                acc = fmaf(qv_p[x*128 + h*16 + d], c_sh[x], acc);
            for (int o = 16; o > 0; o >>= 1) acc += __shfl_down_sync(0xffffffffu, acc, o);
            if (lane == 0) qv_sh[h*16 + d] = acc;
        }
    }
    __syncthreads();

    // ---- attention scores for this half's 4 heads ----
    const int n = hn;
    const int adjv = adj[s_last*N_ + n];
    const bool adj_ok = adjv != 0;
    const bool dem_ok = (n == 0) ? (s_check != 0) : (s_check == 0);

    float m4[4], e4[4];
#pragma unroll
    for (int hh = 0; hh < 4; hh++) {
        int h = half*4 + hh;
        int base = (b*128 + h*16)*N_ + n;
        float acc = 0.f;
#pragma unroll
        for (int d = 0; d < 16; d++) acc = fmaf(qv_sh[h*16 + d], ldg_hint(&g_kv[base + d*N_], PEF), acc);
        m4[hh] = adj_ok ? (dem_ok ? acc*0.25f : -1e10f) : -1e30f;
    }
#pragma unroll
    for (int hh = 0; hh < 4; hh++) {
        float v = m4[hh];
        for (int o = 16; o > 0; o >>= 1) v = fmaxf(v, __shfl_down_sync(0xffffffffu, v, o));
        if (lane == 0) s_redM[half][hwid][hh] = v;
    }
    __syncthreads();
    if (tid < 8) {  // head tid: block max over 16 warp partials (same order as before)
        float x = s_redM[tid>>2][0][tid&3];
        for (int i = 1; i < 16; i++) x = fmaxf(x, s_redM[tid>>2][i][tid&3]);
        s_mx[tid] = x;
    }
    __syncthreads();
#pragma unroll
    for (int hh = 0; hh < 4; hh++) {
        float e = expf_acc(m4[hh] - s_mx[half*4 + hh]);
        e4[hh] = e;
        for (int o = 16; o > 0; o >>= 1) e += __shfl_down_sync(0xffffffffu, e, o);
        if (lane == 0) s_redM[half][hwid][hh] = e;
    }
    __syncthreads();
    if (tid < 8) {  // head tid: block sum over 16 warp partials in warp order (same as before)
        float x = 0.f;
        for (int i = 0; i < 16; i++) x += s_redM[tid>>2][i][tid&3];
        s_sum[tid] = x;
    }
    __syncthreads();
#pragma unroll
    for (int hh = 0; hh < 4; hh++)
        w_sh[half*4 + hh][n] = __fdiv_rn(e4[hh], s_sum[half*4 + hh]);
    __syncthreads();

    // ---- rec via warp-per-row: warp wid handles rows wid*4 .. wid*4+3 ----
    {
        int r0 = wid * 4;
#pragma unroll
        for (int rr = 0; rr < 4; rr++) {
            int r = r0 + rr;            // r = h*16+d
            int h = r >> 4;
            const float* vvp = &g_vv[(b*128 + r)*N_];
            float acc = 0.f;
#pragma unroll
            for (int k = 0; k < 16; k++) {
                int nn = lane + k*32;
                acc = fmaf(w_sh[h][nn], ldg_hint(&vvp[nn], PEL), acc);
            }
            for (int o = 16; o > 0; o >>= 1) acc += __shfl_down_sync(0xffffffffu, acc, o);
            if (lane == 0) rec_sh[r] = acc;
        }
    }
    __syncthreads();

    // ---- FC: hvec_c, qvf ----
    if (tid < 128) {
        float a = 0.f;
        for (int i = 0; i < 128; i++) a = fmaf(ov_p[i*128 + tid], rec_sh[i], a);
        hc_sh[tid] = a;
    }
    __syncthreads();
    if (tid < 128) {
        float a = 0.f;
        for (int v = 0; v < 128; v++) a = fmaf(g_WTqvf[v*128 + tid], hc_sh[v], a);  // coalesced
        qvf_sh[tid] = a + qvf_b[tid];
    }
    __syncthreads();

    // ---- logits + gumbel sample (threads < 512) ----
    float lg = 0.f;
    if (tid < 512) {
        float acc = 0.f;
        int base = b*128*N_ + n;
        for (int u = 0; u < 128; u++) acc = fmaf(qvf_sh[u], ldg_hint(&g_kvf[base + u*N_], PEL), acc);
        const float SQRTU = 11.3137084989847603904f;
        float cf = 10.0f * xla_tanhf(__fdiv_rn(acc, SQRTU));
        lg = adj_ok ? (dem_ok ? cf : -1e10f) : -1e30f;
        logits_sh[n] = lg;
        float g1 = ldg_hint(&g_gum[t*65536 + b*512 + n], PEF);
        float val = lg + g1;

        float bv = val; int bi = n;
#pragma unroll
        for (int o = 16; o > 0; o >>= 1) {
            float ov = __shfl_down_sync(0xffffffffu, bv, o);
            int   oi = __shfl_down_sync(0xffffffffu, bi, o);
            if (ov > bv || (ov == bv && oi < bi)) { bv = ov; bi = oi; }
        }
        float mv = lg;
        for (int o = 16; o > 0; o >>= 1) mv = fmaxf(mv, __shfl_down_sync(0xffffffffu, mv, o));
        if (lane == 0) { s_v[wid] = bv; s_i[wid] = bi; s_m[wid] = mv; }
    }
    __syncthreads();
    if (tid == 0) { float x = s_m[0]; for (int i = 1; i < 16; i++) x = fmaxf(x, s_m[i]); s_gmx = x; }
    __syncthreads();
    if (tid < 512) {
        float ee = expf_acc(lg - s_gmx);
        for (int o = 16; o > 0; o >>= 1) ee += __shfl_down_sync(0xffffffffu, ee, o);
        if (lane == 0) s_s[wid] = ee;
    }
    __syncthreads();
    if (tid == 0) {
        float bbv = s_v[0]; int bbi = s_i[0];
        for (int i = 1; i < 16; i++) {
            if (s_v[i] > bbv || (s_v[i] == bbv && s_i[i] < bbi)) { bbv = s_v[i]; bbi = s_i[i]; }
        }
        float sum = 0.f;
        for (int i = 0; i < 16; i++) sum += s_s[i];
        g_targetA[t & 1][b] = bbi;
        g_logprob[b] = (logits_sh[bbi] - s_gmx) - logf_acc(sum);
    }
}

// ---------------- finalize + output ----------------
__global__ void k_out(float* __restrict__ out, int out_size) {
    int b = threadIdx.x;  // 128 threads, 1 block
    __shared__ float red[128];
    __shared__ int s_t[128];
    __shared__ int s_az;
    s_t[b] = g_targetA[(MSTEPS-1) & 1][b];
    __syncthreads();
    if (b == 0) { int a = 1; for (int i = 0; i < 128; i++) a &= (s_t[i] == 0); s_az = a; }
    __syncthreads();
    int done_prev = g_doneA[(MSTEPS-1) & 1];
    int done_t = (done_prev || s_az) ? 1 : 0;
    int tg = done_prev ? 0 : s_t[b];
    g_route[MSTEPS*B_ + b] = tg;
    if (!done_t) {
        g_flp[b] += g_logprob[b];
        g_len[b] += (tg != 0) ? 1.f : 0.f;
    }
    red[b] = g_flp[b] * g_len[b];
    __syncthreads();
    for (int s = 64; s > 0; s >>= 1) {
        if (b < s) red[b] += red[b + s];
        __syncthreads();
    }
    float loss = red[0] * (1.0f / 128.0f);
    __syncthreads();
    const int R = (MSTEPS+1)*B_;  // 9088
    for (int i = b; i < out_size; i += 128) {
        float v;
        if (i < R)               v = (float)g_route[i];
        else if (i == R)         v = loss;
        else if (i < R + 1 + B_) v = g_flp[i - R - 1];
        else                     v = 0.f;
        out[i] = v;
    }
}

extern "C" void kernel_launch(void* const* d_in, const int* in_sizes, int n_in,
                              void* d_out, int out_size) {
    const float* hvec  = (const float*)d_in[0];
    const float* hbar  = (const float*)d_in[1];
    const int*   adj   = (const int*)  d_in[2];
    const int*   obj   = (const int*)  d_in[3];
    const int*   hml   = (const int*)  d_in[4];
    const float* qv_p  = (const float*)d_in[5];
    const float* kv_p  = (const float*)d_in[6];
    const float* vv_p  = (const float*)d_in[7];
    const float* ov_p  = (const float*)d_in[8];
    const float* qvf_W = (const float*)d_in[9];
    const float* qvf_b = (const float*)d_in[10];
    const float* kvf_W = (const float*)d_in[11];
    const float* kvf_b = (const float*)d_in[12];
    const float* vec_1 = (const float*)d_in[13];
    const float* vec_f = (const float*)d_in[14];
    float* out = (float*)d_out;

    k_init<<<1, 128>>>(obj, hml);
    k_tw<<<64, 256>>>(kvf_W, qvf_W);
    k_gum<<<(MSTEPS*65536)/512, 512>>>();
    k_prep_kv<<<dim3(64, 128), 128>>>(hvec, kv_p, vv_p);
    k_prep_kvf<<<dim3(64, 128), 128>>>(hvec, kvf_b);

    for (int t = 0; t < MSTEPS; t++) {
        k_step<<<128, 1024>>>(t, hvec, hbar, qv_p, adj, vec_1, vec_f,
                              ov_p, qvf_b, obj, hml);
    }
    k_out<<<1, 128>>>(out, out_size);
}

// round 12
// speedup vs baseline: 3.2901x; 1.7194x over previous
#include <cuda_runtime.h>
#include <math.h>

#define B_ 128
#define N_ 512
#define U_ 128
#define MSTEPS 70

// ---------------- device scratch ----------------
__device__ float g_kv [B_*128*N_];     // [b][h*16+d][n]  (streamed, evict_first)
__device__ float g_vv [B_*128*N_];     // [b][h*16+d][n]  (resident, evict_last)
__device__ float g_kvf[B_*U_*N_];      // [b][u][n]       (resident, evict_last)
__device__ float g_gum[MSTEPS*65536];  // precomputed gumbel noise [t][b*512+n]
__device__ float g_WTkvf[U_*U_];       // kvf_W transposed: [v][u]
__device__ float g_WTqvf[U_*U_];       // qvf_W transposed: [v][u]
__device__ float g_qvpT[128*384];      // qv_p transposed: [h*16+d][x]
__device__ int   g_route[(MSTEPS+1)*B_];
__device__ float g_flp[B_];
__device__ float g_len[B_];
__device__ int   g_doneA[2];
__device__ unsigned g_matched[B_];
__device__ int   g_check[B_];
__device__ int   g_targetA[2][B_];
__device__ float g_logprob[B_];
__device__ unsigned g_keys[MSTEPS*2];

// ---------------- Threefry-2x32-20 (JAX partitionable) ----------------
__device__ __forceinline__ void tf2x32(unsigned k0, unsigned k1, unsigned &x0, unsigned &x1) {
    unsigned ks2 = k0 ^ k1 ^ 0x1BD11BDAu;
    x0 += k0; x1 += k1;
#define TFR(r) { x0 += x1; x1 = (x1<<(r)) | (x1>>(32-(r))); x1 ^= x0; }
    TFR(13) TFR(15) TFR(26) TFR(6)
    x0 += k1;  x1 += ks2 + 1u;
    TFR(17) TFR(29) TFR(16) TFR(24)
    x0 += ks2; x1 += k0 + 2u;
    TFR(13) TFR(15) TFR(26) TFR(6)
    x0 += k0;  x1 += k1 + 3u;
    TFR(17) TFR(29) TFR(16) TFR(24)
    x0 += k1;  x1 += ks2 + 4u;
    TFR(13) TFR(15) TFR(26) TFR(6)
    x0 += ks2; x1 += k0 + 5u;
#undef TFR
}

// ---------------- accurate f32 transcendentals (fast-math immune) ----------------
__device__ __forceinline__ float expf_acc(float x) {
    if (x < -87.0f) return 0.f;
    float k = rintf(x * 1.4426950408889634f);
    float r = fmaf(k, -0.693359375f, x);
    r = fmaf(k, 2.12194440e-4f, r);
    float z = r * r;
    float p = 1.9875691500e-4f;
    p = fmaf(p, r, 1.3981999507e-3f);
    p = fmaf(p, r, 8.3334519073e-3f);
    p = fmaf(p, r, 4.1665795894e-2f);
    p = fmaf(p, r, 1.6666665459e-1f);
    p = fmaf(p, r, 5.0000001201e-1f);
    float res = fmaf(z, p, r) + 1.0f;
    int ki = (int)k;
    return res * __int_as_float((ki + 127) << 23);
}

__device__ __forceinline__ float logf_acc(float x) {
    int hx = __float_as_int(x);
    int k = ((hx >> 23) & 0xff) - 127;
    hx = (hx & 0x7fffff) | 0x3f800000;
    float m = __int_as_float(hx);
    if (m >= 1.41421356237f) { m *= 0.5f; k++; }
    float f = m - 1.0f;
    float s = __fdiv_rn(f, 2.0f + f);
    float z = s * s;
    float w = z * z;
    float t1 = w * fmaf(w, 0.24279078841f, 0.40000972152f);
    float t2 = z * fmaf(w, 0.28498786688f, 0.66666662693f);
    float R = t2 + t1;
    float hfsq = 0.5f * f * f;
    float dk = (float)k;
    float r = fmaf(s, hfsq + R, dk * 9.0580006145e-06f);
    return dk * 0.69313812256f - ((hfsq - r) - f);
}

// ---------------- XLA fast-tanh ----------------
__device__ __forceinline__ float xla_tanhf(float x) {
    float ax = fabsf(x);
    const float cl = 7.90531110763549805f;
    float xc = fminf(fmaxf(x, -cl), cl);
    float x2 = xc * xc;
    float p = fmaf(x2, -2.76076847742355e-16f, 2.00018790482477e-13f);
    p = fmaf(x2, p, -8.60467152213735e-11f);
    p = fmaf(x2, p,  5.12229709037114e-08f);
    p = fmaf(x2, p,  1.48572235717979e-05f);
    p = fmaf(x2, p,  6.37261928875436e-04f);
    p = fmaf(x2, p,  4.89352455891786e-03f);
    p = p * xc;
    float q = fmaf(x2, 1.19825839466702e-06f, 1.18534705686654e-04f);
    q = fmaf(x2, q, 2.26843463243900e-03f);
    q = fmaf(x2, q, 4.89352518554385e-03f);
    float r = __fdiv_rn(p, q);
    return (ax < 0.0004f) ? x : r;
}

// ---------------- L2 policy loads ----------------
__device__ __forceinline__ unsigned long long pol_evict_last() {
    unsigned long long p;
    asm("createpolicy.fractional.L2::evict_last.b64 %0, 1.0;" : "=l"(p));
    return p;
}
__device__ __forceinline__ unsigned long long pol_evict_first() {
    unsigned long long p;
    asm("createpolicy.fractional.L2::evict_first.b64 %0, 1.0;" : "=l"(p));
    return p;
}
__device__ __forceinline__ float ldg_hint(const float* p, unsigned long long pol) {
    float v;
    asm("ld.global.nc.L2::cache_hint.f32 %0,[%1],%2;" : "=f"(v) : "l"(p), "l"(pol));
    return v;
}

// ---------------- init ----------------
__global__ void k_init(const int* __restrict__ obj, const int* __restrict__ hml) {
    int b = threadIdx.x;  // 128 threads
    for (int i = b; i < (MSTEPS+1)*B_; i += B_) g_route[i] = 0;
    g_flp[b] = 0.f; g_len[b] = 0.f;
    if (b == 0) { g_doneA[0] = 0; g_doneA[1] = 0; }
    if (b < MSTEPS) {
        unsigned x0 = 0u, x1 = (unsigned)b;
        tf2x32(0u, 42u, x0, x1);
        g_keys[2*b] = x0; g_keys[2*b+1] = x1;
    }
    int lz = 0;
    for (int m = 0; m < 16; m++) lz |= (hml[b*16 + m] == 0);
    int hz = __syncthreads_or(lz);
    unsigned mk = 0;
    for (int m = 0; m < 16; m++) {
        int v = hml[b*16 + m]; int mt = 0;
        for (int k = 0; k < 4; k++) mt |= (obj[k] == v);
        if (mt) mk |= (1u << m);
    }
    if (hz) mk |= 1u;
    g_matched[b] = mk;
    g_check[b] = (mk == 0xFFFFu) ? 1 : 0;
}

// ---------------- transpose FC weights + qv_p (runs once) ----------------
__global__ void k_tw(const float* __restrict__ kvfW, const float* __restrict__ qvfW,
                     const float* __restrict__ qv_p) {
    int i = blockIdx.x * 256 + threadIdx.x;   // 49152 threads
    if (i < 16384) {
        int u = i >> 7, v = i & 127;
        g_WTkvf[v*128 + u] = kvfW[i];
        g_WTqvf[v*128 + u] = qvfW[i];
    }
    // qv_p transpose: [x][r] -> [r][x], r = h*16+d
    int r = i / 384, x = i % 384;             // i covers 128*384 = 49152
    g_qvpT[i] = qv_p[x*128 + r];
}

// ---------------- precompute gumbel noise ----------------
__global__ void k_gum() {
    int idx = blockIdx.x * 512 + threadIdx.x;   // 70*65536 total
    int t = idx >> 16, f = idx & 65535;
    unsigned x0 = 0u, x1 = (unsigned)f;
    tf2x32(g_keys[2*t], g_keys[2*t+1], x0, x1);
    unsigned bits = x0 ^ x1;
    float u0 = __uint_as_float((bits >> 9) | 0x3f800000u) - 1.0f;
    const float TINY = 1.17549435082228751e-38f;
    float uu = fmaxf(TINY, u0 + TINY);
    g_gum[idx] = -logf_acc(-logf_acc(uu));
}

// ---------------- precompute kv, vv (n-tile 16) ----------------
__global__ void k_prep_kv(const float* __restrict__ hvec, const float* __restrict__ kv_p,
                          const float* __restrict__ vv_p) {
    int b = blockIdx.y, n0 = blockIdx.x * 16;
    int t = threadIdx.x;
    __shared__ float hs[16*128];
    for (int i = t; i < 16*128; i += 128)
        hs[i] = hvec[(b*N_ + n0 + (i >> 7))*U_ + (i & 127)];
    __syncthreads();
    float ak[16], av[16];
#pragma unroll
    for (int j = 0; j < 16; j++) { ak[j] = 0.f; av[j] = 0.f; }
    for (int x = 0; x < 128; x++) {
        float kp = kv_p[x*128 + t];
        float vp = vv_p[x*128 + t];
#pragma unroll
        for (int j = 0; j < 16; j++) {
            float hx = hs[j*128 + x];
            ak[j] = fmaf(kp, hx, ak[j]);
            av[j] = fmaf(vp, hx, av[j]);
        }
    }
#pragma unroll
    for (int j = 0; j < 16; j++) {
        g_kv[(b*128 + t)*N_ + n0 + j] = ak[j];
        g_vv[(b*128 + t)*N_ + n0 + j] = av[j];
    }
}

// ---------------- precompute kvf (n-tile 16, coalesced W) ----------------
__global__ void k_prep_kvf(const float* __restrict__ hvec, const float* __restrict__ bias) {
    int b = blockIdx.y, n0 = blockIdx.x * 16;
    int u = threadIdx.x;
    __shared__ float hs[16*128];
    for (int i = u; i < 16*128; i += 128)
        hs[i] = hvec[(b*N_ + n0 + (i >> 7))*U_ + (i & 127)];
    __syncthreads();
    float a[16];
#pragma unroll
    for (int j = 0; j < 16; j++) a[j] = 0.f;
    for (int v = 0; v < 128; v++) {
        float w = g_WTkvf[v*128 + u];
#pragma unroll
        for (int j = 0; j < 16; j++) a[j] = fmaf(w, hs[j*128 + v], a[j]);
    }
    float bb = bias[u];
#pragma unroll
    for (int j = 0; j < 16; j++) g_kvf[(b*128 + u)*N_ + n0 + j] = a[j] + bb;
}

// ---------------- fused per-step kernel ----------------
__global__ void __launch_bounds__(1024, 1)
k_step(int t, const float* __restrict__ hvec, const float* __restrict__ hbar,
       const int* __restrict__ adj,
       const float* __restrict__ vec_1, const float* __restrict__ vec_f,
       const float* __restrict__ ov_p, const float* __restrict__ qvf_b,
       const int* __restrict__ obj, const int* __restrict__ hml) {
    int b = blockIdx.x;
    int tid = threadIdx.x;
    int half = tid >> 9;        // 0 or 1
    int hn   = tid & 511;       // n within half
    int lane = tid & 31;
    int wid  = tid >> 5;        // 0..31
    int hwid = wid & 15;        // warp within half

    __shared__ float c_sh[384];
    __shared__ float qv_sh[128];
    __shared__ float w_sh[8][512];
    __shared__ float s_redM[2][16][4];
    __shared__ float s_mx[8], s_sum[8];
    __shared__ float rec_sh[128];
    __shared__ float hc_sh[128];
    __shared__ float qvf_sh[128];
    __shared__ float logits_sh[512];
    __shared__ float s_v[16]; __shared__ int s_i[16];
    __shared__ float s_m[16], s_s[16];
    __shared__ float s_gmx;
    __shared__ int s_last, s_check, s_done;
    __shared__ int s_t[128];

    unsigned long long PEL = pol_evict_last();
    unsigned long long PEF = pol_evict_first();

    // ---- phase 0: apply previous step's sampled targets (stats) ----
    if (t == 0) {
        if (tid == 0) { s_last = 0; s_check = g_check[b]; s_done = 0; }
    } else {
        if (tid < 128) s_t[tid] = g_targetA[(t-1) & 1][tid];
        __syncthreads();
        if (tid == 0) {
            int done_prev = g_doneA[(t-1) & 1];
            int a = 1;
            for (int i = 0; i < 128; i++) a &= (s_t[i] == 0);
            int done_t = (done_prev || a) ? 1 : 0;
            int tg = done_prev ? 0 : s_t[b];
            g_route[t*B_ + b] = tg;
            if (!done_t) {
                g_flp[b] += g_logprob[b];
                g_len[b] += (tg != 0) ? 1.f : 0.f;
            }
            unsigned mk = g_matched[b];
#pragma unroll
            for (int m = 0; m < 16; m++) {
                int hv = hml[b*16 + m]; int mt = 0;
#pragma unroll
                for (int k2 = 0; k2 < 4; k2++) mt |= (obj[tg*4 + k2] == hv);
                if (mt) mk |= (1u << m);
            }
            g_matched[b] = mk;
            s_last = tg; s_check = (mk == 0xFFFFu) ? 1 : 0; s_done = done_t;
            if (b == 0) g_doneA[t & 1] = done_t;
        }
    }
    __syncthreads();
    if (s_done) return;

    // ---- context vector [hbar | prev_vec | first_vec] ----
    if (tid < 384) {
        float v;
        if (t == 0) {
            v = (tid < 128) ? hbar[tid]
              : (tid < 256) ? vec_1[b*U_ + tid - 128]
                            : vec_f[b*U_ + tid - 256];
        } else {
            int previ  = g_route[(t-1)*B_ + b];
            int firsti = (t == 1) ? s_last : g_route[B_ + b];
            v = (tid < 128) ? hbar[tid]
              : (tid < 256) ? hvec[(b*N_ + previ)*U_ + tid - 128]
                            : hvec[(b*N_ + firsti)*U_ + tid - 256];
        }
        c_sh[tid] = v;
    }
    __syncthreads();

    // ---- qv: coalesced via transposed qv_p ----
    {
        int d = hwid;
        for (int hh = 0; hh < 4; hh++) {
            int h = half*4 + hh;
            const float* qp = &g_qvpT[(h*16 + d)*384];
            float acc = 0.f;
            for (int x = lane; x < 384; x += 32)
                acc = fmaf(qp[x], c_sh[x], acc);
            for (int o = 16; o > 0; o >>= 1) acc += __shfl_down_sync(0xffffffffu, acc, o);
            if (lane == 0) qv_sh[h*16 + d] = acc;
        }
    }
    __syncthreads();

    // ---- attention scores for this half's 4 heads ----
    const int n = hn;
    const int adjv = adj[s_last*N_ + n];
    const bool adj_ok = adjv != 0;
    const bool dem_ok = (n == 0) ? (s_check != 0) : (s_check == 0);

    float m4[4], e4[4];
#pragma unroll
    for (int hh = 0; hh < 4; hh++) {
        int h = half*4 + hh;
        int base = (b*128 + h*16)*N_ + n;
        float acc = 0.f;
#pragma unroll
        for (int d = 0; d < 16; d++) acc = fmaf(qv_sh[h*16 + d], ldg_hint(&g_kv[base + d*N_], PEF), acc);
        m4[hh] = adj_ok ? (dem_ok ? acc*0.25f : -1e10f) : -1e30f;
    }
#pragma unroll
    for (int hh = 0; hh < 4; hh++) {
        float v = m4[hh];
        for (int o = 16; o > 0; o >>= 1) v = fmaxf(v, __shfl_down_sync(0xffffffffu, v, o));
        if (lane == 0) s_redM[half][hwid][hh] = v;
    }
    __syncthreads();
    if (tid < 8) {
        float x = s_redM[tid>>2][0][tid&3];
        for (int i = 1; i < 16; i++) x = fmaxf(x, s_redM[tid>>2][i][tid&3]);
        s_mx[tid] = x;
    }
    __syncthreads();
#pragma unroll
    for (int hh = 0; hh < 4; hh++) {
        float e = expf_acc(m4[hh] - s_mx[half*4 + hh]);
        e4[hh] = e;
        for (int o = 16; o > 0; o >>= 1) e += __shfl_down_sync(0xffffffffu, e, o);
        if (lane == 0) s_redM[half][hwid][hh] = e;
    }
    __syncthreads();
    if (tid < 8) {
        float x = 0.f;
        for (int i = 0; i < 16; i++) x += s_redM[tid>>2][i][tid&3];
        s_sum[tid] = x;
    }
    __syncthreads();
#pragma unroll
    for (int hh = 0; hh < 4; hh++)
        w_sh[half*4 + hh][n] = __fdiv_rn(e4[hh], s_sum[half*4 + hh]);
    __syncthreads();

    // ---- rec via warp-per-row ----
    {
        int r0 = wid * 4;
#pragma unroll
        for (int rr = 0; rr < 4; rr++) {
            int r = r0 + rr;            // r = h*16+d
            int h = r >> 4;
            const float* vvp = &g_vv[(b*128 + r)*N_];
            float acc = 0.f;
#pragma unroll
            for (int k = 0; k < 16; k++) {
                int nn = lane + k*32;
                acc = fmaf(w_sh[h][nn], ldg_hint(&vvp[nn], PEL), acc);
            }
            for (int o = 16; o > 0; o >>= 1) acc += __shfl_down_sync(0xffffffffu, acc, o);
            if (lane == 0) rec_sh[r] = acc;
        }
    }
    __syncthreads();

    // ---- FC: hvec_c, qvf ----
    if (tid < 128) {
        float a = 0.f;
        for (int i = 0; i < 128; i++) a = fmaf(ov_p[i*128 + tid], rec_sh[i], a);
        hc_sh[tid] = a;
    }
    __syncthreads();
    if (tid < 128) {
        float a = 0.f;
        for (int v = 0; v < 128; v++) a = fmaf(g_WTqvf[v*128 + tid], hc_sh[v], a);
        qvf_sh[tid] = a + qvf_b[tid];
    }
    __syncthreads();

    // ---- logits + gumbel sample (threads < 512) ----
    float lg = 0.f;
    if (tid < 512) {
        float acc = 0.f;
        int base = b*128*N_ + n;
        for (int u = 0; u < 128; u++) acc = fmaf(qvf_sh[u], ldg_hint(&g_kvf[base + u*N_], PEL), acc);
        const float SQRTU = 11.3137084989847603904f;
        float cf = 10.0f * xla_tanhf(__fdiv_rn(acc, SQRTU));
        lg = adj_ok ? (dem_ok ? cf : -1e10f) : -1e30f;
        logits_sh[n] = lg;
        float g1 = ldg_hint(&g_gum[t*65536 + b*512 + n], PEF);
        float val = lg + g1;

        float bv = val; int bi = n;
#pragma unroll
        for (int o = 16; o > 0; o >>= 1) {
            float ov = __shfl_down_sync(0xffffffffu, bv, o);
            int   oi = __shfl_down_sync(0xffffffffu, bi, o);
            if (ov > bv || (ov == bv && oi < bi)) { bv = ov; bi = oi; }
        }
        float mv = lg;
        for (int o = 16; o > 0; o >>= 1) mv = fmaxf(mv, __shfl_down_sync(0xffffffffu, mv, o));
        if (lane == 0) { s_v[wid] = bv; s_i[wid] = bi; s_m[wid] = mv; }
    }
    __syncthreads();
    if (tid == 0) { float x = s_m[0]; for (int i = 1; i < 16; i++) x = fmaxf(x, s_m[i]); s_gmx = x; }
    __syncthreads();
    if (tid < 512) {
        float ee = expf_acc(lg - s_gmx);
        for (int o = 16; o > 0; o >>= 1) ee += __shfl_down_sync(0xffffffffu, ee, o);
        if (lane == 0) s_s[wid] = ee;
    }
    __syncthreads();
    if (tid == 0) {
        float bbv = s_v[0]; int bbi = s_i[0];
        for (int i = 1; i < 16; i++) {
            if (s_v[i] > bbv || (s_v[i] == bbv && s_i[i] < bbi)) { bbv = s_v[i]; bbi = s_i[i]; }
        }
        float sum = 0.f;
        for (int i = 0; i < 16; i++) sum += s_s[i];
        g_targetA[t & 1][b] = bbi;
        g_logprob[b] = (logits_sh[bbi] - s_gmx) - logf_acc(sum);
    }
}

// ---------------- finalize + output ----------------
__global__ void k_out(float* __restrict__ out, int out_size) {
    int b = threadIdx.x;  // 128 threads, 1 block
    __shared__ float red[128];
    __shared__ int s_t[128];
    __shared__ int s_az;
    s_t[b] = g_targetA[(MSTEPS-1) & 1][b];
    __syncthreads();
    if (b == 0) { int a = 1; for (int i = 0; i < 128; i++) a &= (s_t[i] == 0); s_az = a; }
    __syncthreads();
    int done_prev = g_doneA[(MSTEPS-1) & 1];
    int done_t = (done_prev || s_az) ? 1 : 0;
    int tg = done_prev ? 0 : s_t[b];
    g_route[MSTEPS*B_ + b] = tg;
    if (!done_t) {
        g_flp[b] += g_logprob[b];
        g_len[b] += (tg != 0) ? 1.f : 0.f;
    }
    red[b] = g_flp[b] * g_len[b];
    __syncthreads();
    for (int s = 64; s > 0; s >>= 1) {
        if (b < s) red[b] += red[b + s];
        __syncthreads();
    }
    float loss = red[0] * (1.0f / 128.0f);
    __syncthreads();
    const int R = (MSTEPS+1)*B_;  // 9088
    for (int i = b; i < out_size; i += 128) {
        float v;
        if (i < R)               v = (float)g_route[i];
        else if (i == R)         v = loss;
        else if (i < R + 1 + B_) v = g_flp[i - R - 1];
        else                     v = 0.f;
        out[i] = v;
    }
}

extern "C" void kernel_launch(void* const* d_in, const int* in_sizes, int n_in,
                              void* d_out, int out_size) {
    const float* hvec  = (const float*)d_in[0];
    const float* hbar  = (const float*)d_in[1];
    const int*   adj   = (const int*)  d_in[2];
    const int*   obj   = (const int*)  d_in[3];
    const int*   hml   = (const int*)  d_in[4];
    const float* qv_p  = (const float*)d_in[5];
    const float* kv_p  = (const float*)d_in[6];
    const float* vv_p  = (const float*)d_in[7];
    const float* ov_p  = (const float*)d_in[8];
    const float* qvf_W = (const float*)d_in[9];
    const float* qvf_b = (const float*)d_in[10];
    const float* kvf_W = (const float*)d_in[11];
    const float* kvf_b = (const float*)d_in[12];
    const float* vec_1 = (const float*)d_in[13];
    const float* vec_f = (const float*)d_in[14];
    float* out = (float*)d_out;

    k_init<<<1, 128>>>(obj, hml);
    k_tw<<<192, 256>>>(kvf_W, qvf_W, qv_p);
    k_gum<<<(MSTEPS*65536)/512, 512>>>();
    k_prep_kv<<<dim3(32, 128), 128>>>(hvec, kv_p, vv_p);
    k_prep_kvf<<<dim3(32, 128), 128>>>(hvec, kvf_b);

    for (int t = 0; t < MSTEPS; t++) {
        k_step<<<128, 1024>>>(t, hvec, hbar, adj, vec_1, vec_f,
                              ov_p, qvf_b, obj, hml);
    }
    k_out<<<1, 128>>>(out, out_size);
}